// round 2
// baseline (speedup 1.0000x reference)
#include <cuda_runtime.h>
#include <math.h>

#define D_MODEL 2048
#define NHEAD   16
#define HDIM    128
#define BATCH   2
#define SEQ     2048
#define MTOT    (BATCH * SEQ)   // 4096

// Scratch (allocation-free; __device__ globals are the sanctioned mechanism)
__device__ float g_Q[(size_t)MTOT * D_MODEL];  // 33.5 MB
__device__ float g_K[(size_t)MTOT * HDIM];     //  2 MB
__device__ float g_V[(size_t)MTOT * HDIM];     //  2 MB
__device__ float g_A[(size_t)MTOT * D_MODEL];  // 33.5 MB

// ---------------------------------------------------------------------------
// SGEMM + bias: C[M,N] = A[M,K] @ B[K,N] + bias[N]
// 128x128 block tile, BK=16, 256 threads, 8x8 per-thread microtile.
// M % 128 == 0, N % 128 == 0, K % 16 == 0 (true for all our shapes).
// ---------------------------------------------------------------------------
__global__ __launch_bounds__(256) void sgemm_bias(
    const float* __restrict__ A, const float* __restrict__ B,
    const float* __restrict__ bias, float* __restrict__ C,
    int M, int N, int K)
{
    __shared__ float As[16][132];   // transposed A tile: As[k][m]
    __shared__ float Bs[16][132];   // Bs[k][n]

    const int tid = threadIdx.x;
    const int m0 = blockIdx.y * 128;
    const int n0 = blockIdx.x * 128;
    const int ty = tid >> 4;          // 0..15 -> C rows ty*8..ty*8+7
    const int tx = tid & 15;          // 0..15 -> C cols tx*8..tx*8+7

    const int ar = tid >> 2;          // 0..63 (A tile rows ar, ar+64)
    const int ac = (tid & 3) << 2;    // 0,4,8,12
    const int br = tid >> 5;          // 0..7  (B tile rows br, br+8)
    const int bc = (tid & 31) << 2;   // 0..124

    float acc[8][8];
    #pragma unroll
    for (int i = 0; i < 8; i++)
        #pragma unroll
        for (int j = 0; j < 8; j++) acc[i][j] = 0.f;

    for (int kk = 0; kk < K; kk += 16) {
        float4 a0 = *(const float4*)(A + (size_t)(m0 + ar)      * K + kk + ac);
        float4 a1 = *(const float4*)(A + (size_t)(m0 + ar + 64) * K + kk + ac);
        float4 b0 = *(const float4*)(B + (size_t)(kk + br)      * N + n0 + bc);
        float4 b1 = *(const float4*)(B + (size_t)(kk + br + 8)  * N + n0 + bc);

        As[ac + 0][ar] = a0.x;  As[ac + 1][ar] = a0.y;
        As[ac + 2][ar] = a0.z;  As[ac + 3][ar] = a0.w;
        As[ac + 0][ar + 64] = a1.x;  As[ac + 1][ar + 64] = a1.y;
        As[ac + 2][ar + 64] = a1.z;  As[ac + 3][ar + 64] = a1.w;
        *(float4*)&Bs[br][bc]     = b0;
        *(float4*)&Bs[br + 8][bc] = b1;
        __syncthreads();

        #pragma unroll
        for (int k = 0; k < 16; k++) {
            float a[8], bb[8];
            *(float4*)&a[0]  = *(const float4*)&As[k][ty * 8];
            *(float4*)&a[4]  = *(const float4*)&As[k][ty * 8 + 4];
            *(float4*)&bb[0] = *(const float4*)&Bs[k][tx * 8];
            *(float4*)&bb[4] = *(const float4*)&Bs[k][tx * 8 + 4];
            #pragma unroll
            for (int i = 0; i < 8; i++)
                #pragma unroll
                for (int j = 0; j < 8; j++)
                    acc[i][j] = fmaf(a[i], bb[j], acc[i][j]);
        }
        __syncthreads();
    }

    #pragma unroll
    for (int i = 0; i < 8; i++) {
        size_t row = (size_t)(m0 + ty * 8 + i);
        #pragma unroll
        for (int j = 0; j < 8; j += 4) {
            int col = n0 + tx * 8 + j;
            float4 o;
            o.x = acc[i][j + 0] + bias[col + 0];
            o.y = acc[i][j + 1] + bias[col + 1];
            o.z = acc[i][j + 2] + bias[col + 2];
            o.w = acc[i][j + 3] + bias[col + 3];
            *(float4*)(C + row * N + col) = o;
        }
    }
}

// ---------------------------------------------------------------------------
// Flash MQA: per (b, h, q-tile of 64 rows). One shared K/V head.
// BM=64, BN=64, d=128, fp32, online softmax.
// smem: s_qt[128][68] transposed Q, s_kt[128][68] transposed K
//       (P-tile [64][68] ALIASES s_kt after scores are consumed),
//       s_v[64][128]. Total 102400 B -> 2 CTAs/SM.
// Thread map: ty=tid/16 owns rows 4ty..4ty+3; tx=tid%16.
//   Score phase: thread owns 4x4 scores (keys 4tx..4tx+3).
//   Acc phase:   thread owns 4 rows x 8 dims (dims 8tx..8tx+7).
// Row reductions: 16-lane shuffle butterfly (one row group = contiguous 16 lanes).
// ---------------------------------------------------------------------------
#define FS_QK 68

__global__ __launch_bounds__(256, 2) void mqa_flash(
    const float* __restrict__ gQ, const float* __restrict__ gK,
    const float* __restrict__ gV, float* __restrict__ gO)
{
    extern __shared__ float sm[];
    float* s_qt = sm;                     // [128][FS_QK]
    float* s_kt = sm + 128 * FS_QK;       // [128][FS_QK]
    float* s_pt = s_kt;                   // alias, [64][FS_QK]
    float* s_v  = sm + 2 * 128 * FS_QK;   // [64][HDIM]

    const int tid = threadIdx.x;
    const int ty = tid >> 4;    // 0..15
    const int tx = tid & 15;    // 0..15
    const int b  = blockIdx.z;
    const int h  = blockIdx.y;
    const int q0 = blockIdx.x * 64;
    const float scale = 0.08838834764831845f;   // 1/sqrt(128)

    // Load Q tile transposed (pre-scaled)
    const float* qb = gQ + (size_t)(b * SEQ + q0) * D_MODEL + h * HDIM;
    for (int i = tid; i < 64 * 32; i += 256) {
        int r = i >> 5;
        int d = (i & 31) << 2;
        float4 v = *(const float4*)(qb + (size_t)r * D_MODEL + d);
        s_qt[(d + 0) * FS_QK + r] = v.x * scale;
        s_qt[(d + 1) * FS_QK + r] = v.y * scale;
        s_qt[(d + 2) * FS_QK + r] = v.z * scale;
        s_qt[(d + 3) * FS_QK + r] = v.w * scale;
    }

    float m_i[4], l_i[4], acc[4][8];
    #pragma unroll
    for (int i = 0; i < 4; i++) {
        m_i[i] = -1e30f;
        l_i[i] = 0.f;
        #pragma unroll
        for (int j = 0; j < 8; j++) acc[i][j] = 0.f;
    }
    __syncthreads();

    for (int kt = 0; kt < SEQ; kt += 64) {
        // Load K (transposed) and V tiles
        const float* kb = gK + (size_t)(b * SEQ + kt) * HDIM;
        const float* vb = gV + (size_t)(b * SEQ + kt) * HDIM;
        for (int i = tid; i < 64 * 32; i += 256) {
            int r = i >> 5;
            int d = (i & 31) << 2;
            float4 v = *(const float4*)(kb + r * HDIM + d);
            s_kt[(d + 0) * FS_QK + r] = v.x;
            s_kt[(d + 1) * FS_QK + r] = v.y;
            s_kt[(d + 2) * FS_QK + r] = v.z;
            s_kt[(d + 3) * FS_QK + r] = v.w;
            *(float4*)(s_v + r * HDIM + d) = *(const float4*)(vb + r * HDIM + d);
        }
        __syncthreads();

        // Scores: c[i][j] = (scaled Q row 4ty+i) . (K row kt+4tx+j)
        float c[4][4];
        #pragma unroll
        for (int i = 0; i < 4; i++)
            #pragma unroll
            for (int j = 0; j < 4; j++) c[i][j] = 0.f;

        #pragma unroll 4
        for (int d = 0; d < 128; d++) {
            float4 qa = *(const float4*)(s_qt + d * FS_QK + 4 * ty);
            float4 ka = *(const float4*)(s_kt + d * FS_QK + 4 * tx);
            float qv[4] = {qa.x, qa.y, qa.z, qa.w};
            float kv[4] = {ka.x, ka.y, ka.z, ka.w};
            #pragma unroll
            for (int i = 0; i < 4; i++)
                #pragma unroll
                for (int j = 0; j < 4; j++)
                    c[i][j] = fmaf(qv[i], kv[j], c[i][j]);
        }
        __syncthreads();   // all score reads of s_kt done -> safe to alias

        // Online softmax (row group = 16 contiguous lanes)
        float p[4][4];
        #pragma unroll
        for (int i = 0; i < 4; i++) {
            float tmax = fmaxf(fmaxf(c[i][0], c[i][1]), fmaxf(c[i][2], c[i][3]));
            #pragma unroll
            for (int off = 8; off; off >>= 1)
                tmax = fmaxf(tmax, __shfl_xor_sync(0xffffffffu, tmax, off));
            float mnew = fmaxf(m_i[i], tmax);
            float corr = __expf(m_i[i] - mnew);
            float rs = 0.f;
            #pragma unroll
            for (int j = 0; j < 4; j++) {
                p[i][j] = __expf(c[i][j] - mnew);
                rs += p[i][j];
            }
            #pragma unroll
            for (int off = 8; off; off >>= 1)
                rs += __shfl_xor_sync(0xffffffffu, rs, off);
            l_i[i] = l_i[i] * corr + rs;
            m_i[i] = mnew;
            #pragma unroll
            for (int j = 0; j < 8; j++) acc[i][j] *= corr;
        }

        // Write P transposed into aliased region: s_pt[key][row]
        #pragma unroll
        for (int j = 0; j < 4; j++)
            #pragma unroll
            for (int i = 0; i < 4; i++)
                s_pt[(4 * tx + j) * FS_QK + 4 * ty + i] = p[i][j];
        __syncthreads();

        // acc += P^T-tile @ V-tile : rows 4ty.., dims 8tx..
        #pragma unroll 4
        for (int k = 0; k < 64; k++) {
            float4 p4  = *(const float4*)(s_pt + k * FS_QK + 4 * ty);
            float4 va  = *(const float4*)(s_v + k * HDIM + 8 * tx);
            float4 vb4 = *(const float4*)(s_v + k * HDIM + 8 * tx + 4);
            float pv[4] = {p4.x, p4.y, p4.z, p4.w};
            float vv[8] = {va.x, va.y, va.z, va.w, vb4.x, vb4.y, vb4.z, vb4.w};
            #pragma unroll
            for (int i = 0; i < 4; i++)
                #pragma unroll
                for (int j = 0; j < 8; j++)
                    acc[i][j] = fmaf(pv[i], vv[j], acc[i][j]);
        }
        __syncthreads();   // protect s_pt/s_v before next tile load
    }

    // Normalize and write out in [b, s, h*d] layout
    #pragma unroll
    for (int i = 0; i < 4; i++) {
        float inv = 1.0f / l_i[i];
        size_t row = (size_t)(b * SEQ + q0 + 4 * ty + i);
        float* o = gO + row * D_MODEL + h * HDIM + 8 * tx;
        float4 o0 = {acc[i][0] * inv, acc[i][1] * inv, acc[i][2] * inv, acc[i][3] * inv};
        float4 o1 = {acc[i][4] * inv, acc[i][5] * inv, acc[i][6] * inv, acc[i][7] * inv};
        *(float4*)o       = o0;
        *(float4*)(o + 4) = o1;
    }
}

// ---------------------------------------------------------------------------
extern "C" void kernel_launch(void* const* d_in, const int* in_sizes, int n_in,
                              void* d_out, int out_size)
{
    const float* query = (const float*)d_in[0];
    const float* key   = (const float*)d_in[1];
    const float* value = (const float*)d_in[2];
    const float* Wq    = (const float*)d_in[3];
    const float* bq    = (const float*)d_in[4];
    const float* Wk    = (const float*)d_in[5];
    const float* bk    = (const float*)d_in[6];
    const float* Wv    = (const float*)d_in[7];
    const float* bv    = (const float*)d_in[8];
    const float* Wo    = (const float*)d_in[9];
    const float* bo    = (const float*)d_in[10];
    float* out = (float*)d_out;

    float *pQ, *pK, *pV, *pA;
    cudaGetSymbolAddress((void**)&pQ, g_Q);
    cudaGetSymbolAddress((void**)&pK, g_K);
    cudaGetSymbolAddress((void**)&pV, g_V);
    cudaGetSymbolAddress((void**)&pA, g_A);

    const size_t FLASH_SMEM = (size_t)(2 * 128 * FS_QK + 64 * HDIM) * sizeof(float); // 102400
    cudaFuncSetAttribute(mqa_flash, cudaFuncAttributeMaxDynamicSharedMemorySize,
                         (int)FLASH_SMEM);

    dim3 blk(256);
    // Projections
    sgemm_bias<<<dim3(D_MODEL / 128, MTOT / 128), blk>>>(query, Wq, bq, pQ, MTOT, D_MODEL, D_MODEL);
    sgemm_bias<<<dim3(1, MTOT / 128), blk>>>(key,   Wk, bk, pK, MTOT, HDIM, D_MODEL);
    sgemm_bias<<<dim3(1, MTOT / 128), blk>>>(value, Wv, bv, pV, MTOT, HDIM, D_MODEL);
    // Attention
    mqa_flash<<<dim3(SEQ / 64, NHEAD, BATCH), blk, FLASH_SMEM>>>(pQ, pK, pV, pA);
    // Output projection
    sgemm_bias<<<dim3(D_MODEL / 128, MTOT / 128), blk>>>(pA, Wo, bo, out, MTOT, D_MODEL, D_MODEL);
}

// round 8
// speedup vs baseline: 3.0511x; 3.0511x over previous
#include <cuda_runtime.h>
#include <math.h>
#include <stdint.h>

#define D_MODEL 2048
#define NHEAD   16
#define HDIM    128
#define BATCH   2
#define SEQ     2048
#define MTOT    (BATCH * SEQ)   // 4096

// ---------------- scratch (allocation-free) ----------------
__device__ float g_Q [(size_t)MTOT * D_MODEL];
__device__ float g_K [(size_t)MTOT * HDIM];
__device__ float g_V [(size_t)MTOT * HDIM];
__device__ float g_A [(size_t)MTOT * D_MODEL];
__device__ float g_Qr[(size_t)MTOT * D_MODEL];   // tf32-rounded inputs
__device__ float g_Kr[(size_t)MTOT * D_MODEL];
__device__ float g_Vr[(size_t)MTOT * D_MODEL];
__device__ float g_Wqt[(size_t)D_MODEL * D_MODEL];
__device__ float g_Wot[(size_t)D_MODEL * D_MODEL];
__device__ float g_Wkt[(size_t)HDIM * D_MODEL];
__device__ float g_Wvt[(size_t)HDIM * D_MODEL];

// ---------------- helpers ----------------
__device__ __forceinline__ uint32_t f2tf(float x) {
    uint32_t r;
    asm("cvt.rna.tf32.f32 %0, %1;" : "=r"(r) : "f"(x));
    return r;
}
__device__ __forceinline__ float f2tff(float x) { return __uint_as_float(f2tf(x)); }

__device__ __forceinline__ void mma_tf32(float* d, const uint32_t* a, uint32_t b0, uint32_t b1) {
    asm volatile(
        "mma.sync.aligned.m16n8k8.row.col.f32.tf32.tf32.f32 "
        "{%0,%1,%2,%3}, {%4,%5,%6,%7}, {%8,%9}, {%0,%1,%2,%3};"
        : "+f"(d[0]), "+f"(d[1]), "+f"(d[2]), "+f"(d[3])
        : "r"(a[0]), "r"(a[1]), "r"(a[2]), "r"(a[3]), "r"(b0), "r"(b1));
}

__device__ __forceinline__ void cp_async16(void* dst, const void* src) {
    uint32_t d;
    asm("{ .reg .u64 t; cvta.to.shared.u64 t, %1; cvt.u32.u64 %0, t; }" : "=r"(d) : "l"(dst));
    asm volatile("cp.async.cg.shared.global [%0], [%1], 16;" :: "r"(d), "l"(src) : "memory");
}
__device__ __forceinline__ void cp_commit() {
    asm volatile("cp.async.commit_group;" ::: "memory");
}
template <int N> __device__ __forceinline__ void cp_wait() {
    asm volatile("cp.async.wait_group %0;" :: "n"(N) : "memory");
}

// ---------------------------------------------------------------------------
// round_copy: tf32-round a fp32 array (vectorized)
// ---------------------------------------------------------------------------
__global__ void round_copy(const float* __restrict__ in, float* __restrict__ out, int n4) {
    int i = blockIdx.x * 256 + threadIdx.x;
    if (i < n4) {
        float4 v = ((const float4*)in)[i];
        v.x = f2tff(v.x); v.y = f2tff(v.y); v.z = f2tff(v.z); v.w = f2tff(v.w);
        ((float4*)out)[i] = v;
    }
}

// ---------------------------------------------------------------------------
// transpose + tf32 round: out[c][r] = round(in[r][c]). grid (C/32, R/32), block (32,8)
// ---------------------------------------------------------------------------
__global__ void transpose_cvt(const float* __restrict__ in, float* __restrict__ out,
                              int R, int C) {
    __shared__ float t[32][33];
    int c0 = blockIdx.x * 32, r0 = blockIdx.y * 32;
    for (int i = threadIdx.y; i < 32; i += 8)
        t[i][threadIdx.x] = in[(size_t)(r0 + i) * C + c0 + threadIdx.x];
    __syncthreads();
    for (int i = threadIdx.y; i < 32; i += 8)
        out[(size_t)(c0 + i) * R + r0 + threadIdx.x] = f2tff(t[threadIdx.x][i]);
}

// ---------------------------------------------------------------------------
// tf32 mma.sync GEMM + bias: C[M,N] = A[M,K] @ Bt[N,K]^T + bias[N]
// CTA 128x128, BK=32, 256 thr = 8 warps (2m x 4n), warp tile 64x32.
// 2-stage cp.async pipeline. Operands pre-rounded to tf32 in gmem.
// Smem stride 36 floats -> conflict-free fragment loads (bank = 4g+c).
// ---------------------------------------------------------------------------
#define GST    36
#define GTILE  (128 * GST)        // 4608 floats
#define GSTAGE (2 * GTILE)        // 9216 floats
#define GSMEM_BYTES (2 * GSTAGE * 4)   // 73728

__global__ __launch_bounds__(256, 2) void gemm_tf32(
    const float* __restrict__ A, const float* __restrict__ Bt,
    const float* __restrict__ bias, float* __restrict__ C,
    int M, int N, int K)
{
    extern __shared__ float sm[];
    const int tid  = threadIdx.x;
    const int wid  = tid >> 5, lane = tid & 31;
    const int g    = lane >> 2, c = lane & 3;
    const int wm   = wid & 1,  wn = wid >> 1;
    const int m0   = blockIdx.y * 128, n0 = blockIdx.x * 128;
    const int NCH  = K >> 5;
    const int srow = tid >> 1;            // 0..127
    const int scc  = (tid & 1) << 2;      // 0 or 4

    float acc[4][4][4];
    #pragma unroll
    for (int i = 0; i < 4; i++)
        #pragma unroll
        for (int j = 0; j < 4; j++)
            #pragma unroll
            for (int k = 0; k < 4; k++) acc[i][j][k] = 0.f;

    // stage loader: 128 rows x 8 f4 per operand = 1024 f4; 2 thr/row x 4 f4 each
    auto load_stage = [&](int ch, int s) {
        float* sA = sm + s * GSTAGE;
        float* sB = sA + GTILE;
        const float* gA = A  + (size_t)m0 * K + ch * 32;
        const float* gB = Bt + (size_t)n0 * K + ch * 32;
        #pragma unroll
        for (int it = 0; it < 4; it++) {
            int cc = scc + it * 8;        // even tid: 0,8,16,24; odd: 4,12,20,28
            cp_async16(sA + srow * GST + cc, gA + (size_t)srow * K + cc);
            cp_async16(sB + srow * GST + cc, gB + (size_t)srow * K + cc);
        }
    };

    load_stage(0, 0);
    cp_commit();

    for (int ch = 0; ch < NCH; ch++) {
        if (ch + 1 < NCH) {
            load_stage(ch + 1, (ch + 1) & 1);
            cp_commit();
            cp_wait<1>();
        } else {
            cp_wait<0>();
        }
        __syncthreads();

        const float* sA = sm + (ch & 1) * GSTAGE;
        const float* sB = sA + GTILE;
        #pragma unroll
        for (int kf = 0; kf < 4; kf++) {
            uint32_t a[4][4], b[4][2];
            #pragma unroll
            for (int mf = 0; mf < 4; mf++) {
                const float* p = sA + (wm * 64 + mf * 16 + g) * GST + kf * 8 + c;
                a[mf][0] = __float_as_uint(p[0]);
                a[mf][1] = __float_as_uint(p[8 * GST]);
                a[mf][2] = __float_as_uint(p[4]);
                a[mf][3] = __float_as_uint(p[8 * GST + 4]);
            }
            #pragma unroll
            for (int nf = 0; nf < 4; nf++) {
                const float* p = sB + (wn * 32 + nf * 8 + g) * GST + kf * 8 + c;
                b[nf][0] = __float_as_uint(p[0]);
                b[nf][1] = __float_as_uint(p[4]);
            }
            #pragma unroll
            for (int mf = 0; mf < 4; mf++)
                #pragma unroll
                for (int nf = 0; nf < 4; nf++)
                    mma_tf32(acc[mf][nf], a[mf], b[nf][0], b[nf][1]);
        }
        __syncthreads();
    }

    // epilogue
    #pragma unroll
    for (int mf = 0; mf < 4; mf++) {
        int r0 = m0 + wm * 64 + mf * 16 + g;
        #pragma unroll
        for (int nf = 0; nf < 4; nf++) {
            int cb = n0 + wn * 32 + nf * 8 + 2 * c;
            float2 bi = *(const float2*)(bias + cb);
            float2 v0 = { acc[mf][nf][0] + bi.x, acc[mf][nf][1] + bi.y };
            float2 v1 = { acc[mf][nf][2] + bi.x, acc[mf][nf][3] + bi.y };
            *(float2*)(C + (size_t)r0 * N + cb)       = v0;
            *(float2*)(C + (size_t)(r0 + 8) * N + cb) = v1;
        }
    }
}

// ---------------------------------------------------------------------------
// Flash MQA with mma.sync tf32. BM=64 q-rows, BN=64 keys, d=128.
// 128 thr = 4 warps, each warp 16 q-rows. 2 CTAs/SM.
// s_q [64][132], s_k [64][132] (P [16][68]/warp aliased over it), s_v [64][136].
// All fragment LDS conflict-free by stride choice.
// ---------------------------------------------------------------------------
#define FQS 132
#define FKS 132
#define FVS 136
#define FPS 68
#define OFF_Q 0
#define OFF_K 8448                 // 64*132
#define OFF_V (8448 + 8704)        // K-slot padded to 8704 floats for P alias
#define FLASH_BYTES ((OFF_V + 64 * FVS) * 4)   // 103424

__global__ __launch_bounds__(128, 2) void mqa_flash(
    const float* __restrict__ gQ, const float* __restrict__ gK,
    const float* __restrict__ gV, float* __restrict__ gO)
{
    extern __shared__ float sm[];
    float* s_q = sm + OFF_Q;
    float* s_k = sm + OFF_K;
    float* s_v = sm + OFF_V;

    const int tid = threadIdx.x;
    const int wid = tid >> 5, lane = tid & 31;
    const int g = lane >> 2, c = lane & 3;
    float* s_p = sm + OFF_K + wid * 16 * FPS;   // per-warp P tile (alias over s_k)

    const int b = blockIdx.z, h = blockIdx.y, q0 = blockIdx.x * 64;
    const float scale = 0.08838834764831845f;   // 1/sqrt(128)

    // stage Q (scaled + tf32 rounded): 64 rows x 32 f4 = 2048 f4 / 128 thr
    const float* qg = gQ + (size_t)(b * SEQ + q0) * D_MODEL + h * HDIM;
    #pragma unroll
    for (int it = 0; it < 16; it++) {
        int i = tid + it * 128;
        int row = i >> 5, dq = (i & 31) << 2;
        float4 v = *(const float4*)(qg + (size_t)row * D_MODEL + dq);
        s_q[row * FQS + dq + 0] = f2tff(v.x * scale);
        s_q[row * FQS + dq + 1] = f2tff(v.y * scale);
        s_q[row * FQS + dq + 2] = f2tff(v.z * scale);
        s_q[row * FQS + dq + 3] = f2tff(v.w * scale);
    }

    float m0v = -1e30f, m1v = -1e30f, l0 = 0.f, l1 = 0.f;
    float acc[16][4];
    #pragma unroll
    for (int i = 0; i < 16; i++)
        #pragma unroll
        for (int j = 0; j < 4; j++) acc[i][j] = 0.f;
    __syncthreads();

    for (int kt = 0; kt < SEQ; kt += 64) {
        const float* kg = gK + (size_t)(b * SEQ + kt) * HDIM;
        const float* vg = gV + (size_t)(b * SEQ + kt) * HDIM;
        #pragma unroll
        for (int it = 0; it < 16; it++) {
            int i = tid + it * 128;
            int row = i >> 5, dq = (i & 31) << 2;
            float4 kv = *(const float4*)(kg + (size_t)row * HDIM + dq);
            s_k[row * FKS + dq + 0] = f2tff(kv.x);
            s_k[row * FKS + dq + 1] = f2tff(kv.y);
            s_k[row * FKS + dq + 2] = f2tff(kv.z);
            s_k[row * FKS + dq + 3] = f2tff(kv.w);
            float4 vv = *(const float4*)(vg + (size_t)row * HDIM + dq);
            s_v[row * FVS + dq + 0] = f2tff(vv.x);
            s_v[row * FVS + dq + 1] = f2tff(vv.y);
            s_v[row * FVS + dq + 2] = f2tff(vv.z);
            s_v[row * FVS + dq + 3] = f2tff(vv.w);
        }
        __syncthreads();

        // --- scores: S[16 x 64] per warp ---
        float sf[8][4];
        #pragma unroll
        for (int nf = 0; nf < 8; nf++)
            #pragma unroll
            for (int j = 0; j < 4; j++) sf[nf][j] = 0.f;

        #pragma unroll
        for (int kf = 0; kf < 16; kf++) {
            uint32_t a[4];
            const float* p = s_q + (wid * 16 + g) * FQS + kf * 8 + c;
            a[0] = __float_as_uint(p[0]);
            a[1] = __float_as_uint(p[8 * FQS]);
            a[2] = __float_as_uint(p[4]);
            a[3] = __float_as_uint(p[8 * FQS + 4]);
            #pragma unroll
            for (int nf = 0; nf < 8; nf++) {
                const float* q = s_k + (nf * 8 + g) * FKS + kf * 8 + c;
                mma_tf32(sf[nf], a, __float_as_uint(q[0]), __float_as_uint(q[4]));
            }
        }
        __syncthreads();   // all warps done reading s_k -> safe to alias with P

        // --- online softmax (thread rows: g and g+8 within warp tile) ---
        float tmax0 = -1e30f, tmax1 = -1e30f;
        #pragma unroll
        for (int nf = 0; nf < 8; nf++) {
            tmax0 = fmaxf(tmax0, fmaxf(sf[nf][0], sf[nf][1]));
            tmax1 = fmaxf(tmax1, fmaxf(sf[nf][2], sf[nf][3]));
        }
        #pragma unroll
        for (int off = 1; off <= 2; off <<= 1) {
            tmax0 = fmaxf(tmax0, __shfl_xor_sync(0xffffffffu, tmax0, off));
            tmax1 = fmaxf(tmax1, __shfl_xor_sync(0xffffffffu, tmax1, off));
        }
        float mn0 = fmaxf(m0v, tmax0), mn1 = fmaxf(m1v, tmax1);
        float corr0 = __expf(m0v - mn0), corr1 = __expf(m1v - mn1);
        float rs0 = 0.f, rs1 = 0.f;
        float pv[8][4];
        #pragma unroll
        for (int nf = 0; nf < 8; nf++) {
            pv[nf][0] = __expf(sf[nf][0] - mn0);
            pv[nf][1] = __expf(sf[nf][1] - mn0);
            pv[nf][2] = __expf(sf[nf][2] - mn1);
            pv[nf][3] = __expf(sf[nf][3] - mn1);
            rs0 += pv[nf][0] + pv[nf][1];
            rs1 += pv[nf][2] + pv[nf][3];
        }
        #pragma unroll
        for (int off = 1; off <= 2; off <<= 1) {
            rs0 += __shfl_xor_sync(0xffffffffu, rs0, off);
            rs1 += __shfl_xor_sync(0xffffffffu, rs1, off);
        }
        l0 = l0 * corr0 + rs0;  m0v = mn0;
        l1 = l1 * corr1 + rs1;  m1v = mn1;
        #pragma unroll
        for (int nf = 0; nf < 16; nf++) {
            acc[nf][0] *= corr0;  acc[nf][1] *= corr0;
            acc[nf][2] *= corr1;  acc[nf][3] *= corr1;
        }

        // store P (tf32-rounded) into per-warp tile
        #pragma unroll
        for (int nf = 0; nf < 8; nf++) {
            uint2 w0 = { f2tf(pv[nf][0]), f2tf(pv[nf][1]) };
            uint2 w1 = { f2tf(pv[nf][2]), f2tf(pv[nf][3]) };
            *(uint2*)(s_p + g * FPS + nf * 8 + 2 * c)       = w0;
            *(uint2*)(s_p + (g + 8) * FPS + nf * 8 + 2 * c) = w1;
        }
        __syncwarp();

        // --- PV: acc[16x128] += P[16x64] @ V[64x128] ---
        #pragma unroll
        for (int kf = 0; kf < 8; kf++) {
            uint32_t a[4];
            const float* p = s_p + g * FPS + kf * 8 + c;
            a[0] = __float_as_uint(p[0]);
            a[1] = __float_as_uint(p[8 * FPS]);
            a[2] = __float_as_uint(p[4]);
            a[3] = __float_as_uint(p[8 * FPS + 4]);
            #pragma unroll
            for (int nf = 0; nf < 16; nf++) {
                const float* q = s_v + (kf * 8 + c) * FVS + nf * 8 + g;
                mma_tf32(acc[nf], a, __float_as_uint(q[0]), __float_as_uint(q[4 * FVS]));
            }
        }
        __syncthreads();   // done with s_p (alias) and s_v before next staging
    }

    // epilogue: normalize + tf32-round (feeds O-proj as A operand)
    float inv0 = 1.f / l0, inv1 = 1.f / l1;
    float* o0 = gO + (size_t)(b * SEQ + q0 + wid * 16 + g) * D_MODEL + h * HDIM;
    float* o1 = o0 + 8 * D_MODEL;
    #pragma unroll
    for (int nf = 0; nf < 16; nf++) {
        int cb = nf * 8 + 2 * c;
        float2 v0 = { f2tff(acc[nf][0] * inv0), f2tff(acc[nf][1] * inv0) };
        float2 v1 = { f2tff(acc[nf][2] * inv1), f2tff(acc[nf][3] * inv1) };
        *(float2*)(o0 + cb) = v0;
        *(float2*)(o1 + cb) = v1;
    }
}

// ---------------------------------------------------------------------------
extern "C" void kernel_launch(void* const* d_in, const int* in_sizes, int n_in,
                              void* d_out, int out_size)
{
    const float* query = (const float*)d_in[0];
    const float* key   = (const float*)d_in[1];
    const float* value = (const float*)d_in[2];
    const float* Wq    = (const float*)d_in[3];
    const float* bq    = (const float*)d_in[4];
    const float* Wk    = (const float*)d_in[5];
    const float* bk    = (const float*)d_in[6];
    const float* Wv    = (const float*)d_in[7];
    const float* bv    = (const float*)d_in[8];
    const float* Wo    = (const float*)d_in[9];
    const float* bo    = (const float*)d_in[10];
    float* out = (float*)d_out;

    float *pQ, *pK, *pV, *pA, *pQr, *pKr, *pVr, *pWqt, *pWot, *pWkt, *pWvt;
    cudaGetSymbolAddress((void**)&pQ,  g_Q);
    cudaGetSymbolAddress((void**)&pK,  g_K);
    cudaGetSymbolAddress((void**)&pV,  g_V);
    cudaGetSymbolAddress((void**)&pA,  g_A);
    cudaGetSymbolAddress((void**)&pQr, g_Qr);
    cudaGetSymbolAddress((void**)&pKr, g_Kr);
    cudaGetSymbolAddress((void**)&pVr, g_Vr);
    cudaGetSymbolAddress((void**)&pWqt, g_Wqt);
    cudaGetSymbolAddress((void**)&pWot, g_Wot);
    cudaGetSymbolAddress((void**)&pWkt, g_Wkt);
    cudaGetSymbolAddress((void**)&pWvt, g_Wvt);

    cudaFuncSetAttribute(gemm_tf32, cudaFuncAttributeMaxDynamicSharedMemorySize, GSMEM_BYTES);
    cudaFuncSetAttribute(mqa_flash, cudaFuncAttributeMaxDynamicSharedMemorySize, FLASH_BYTES);

    const int n4 = MTOT * D_MODEL / 4;   // 2M float4
    round_copy<<<n4 / 256, 256>>>(query, pQr, n4);
    round_copy<<<n4 / 256, 256>>>(key,   pKr, n4);
    round_copy<<<n4 / 256, 256>>>(value, pVr, n4);

    dim3 tb(32, 8);
    transpose_cvt<<<dim3(D_MODEL / 32, D_MODEL / 32), tb>>>(Wq, pWqt, D_MODEL, D_MODEL);
    transpose_cvt<<<dim3(HDIM / 32,    D_MODEL / 32), tb>>>(Wk, pWkt, D_MODEL, HDIM);
    transpose_cvt<<<dim3(HDIM / 32,    D_MODEL / 32), tb>>>(Wv, pWvt, D_MODEL, HDIM);
    transpose_cvt<<<dim3(D_MODEL / 32, D_MODEL / 32), tb>>>(Wo, pWot, D_MODEL, D_MODEL);

    gemm_tf32<<<dim3(D_MODEL / 128, MTOT / 128), 256, GSMEM_BYTES>>>(pQr, pWqt, bq, pQ, MTOT, D_MODEL, D_MODEL);
    gemm_tf32<<<dim3(1,             MTOT / 128), 256, GSMEM_BYTES>>>(pKr, pWkt, bk, pK, MTOT, HDIM,    D_MODEL);
    gemm_tf32<<<dim3(1,             MTOT / 128), 256, GSMEM_BYTES>>>(pVr, pWvt, bv, pV, MTOT, HDIM,    D_MODEL);

    mqa_flash<<<dim3(SEQ / 64, NHEAD, BATCH), 128, FLASH_BYTES>>>(pQ, pK, pV, pA);

    gemm_tf32<<<dim3(D_MODEL / 128, MTOT / 128), 256, GSMEM_BYTES>>>(pA, pWot, bo, out, MTOT, D_MODEL, D_MODEL);
}

// round 11
// speedup vs baseline: 3.8184x; 1.2515x over previous
#include <cuda_runtime.h>
#include <math.h>
#include <stdint.h>

#define D_MODEL 2048
#define NHEAD   16
#define HDIM    128
#define BATCH   2
#define SEQ     2048
#define MTOT    (BATCH * SEQ)   // 4096

// ---------------- scratch (allocation-free) ----------------
__device__ float g_Q [(size_t)MTOT * D_MODEL];
__device__ float g_K [(size_t)MTOT * HDIM];
__device__ float g_V [(size_t)MTOT * HDIM];
__device__ float g_A [(size_t)MTOT * D_MODEL];
__device__ float g_Qr[(size_t)MTOT * D_MODEL];   // tf32-rounded inputs
__device__ float g_Kr[(size_t)MTOT * D_MODEL];
__device__ float g_Vr[(size_t)MTOT * D_MODEL];
__device__ float g_Wqt[(size_t)D_MODEL * D_MODEL];
__device__ float g_Wot[(size_t)D_MODEL * D_MODEL];
__device__ float g_Wkt[(size_t)HDIM * D_MODEL];
__device__ float g_Wvt[(size_t)HDIM * D_MODEL];

// ---------------- helpers ----------------
__device__ __forceinline__ uint32_t f2tf(float x) {
    uint32_t r;
    asm("cvt.rna.tf32.f32 %0, %1;" : "=r"(r) : "f"(x));
    return r;
}
__device__ __forceinline__ float f2tff(float x) { return __uint_as_float(f2tf(x)); }

__device__ __forceinline__ void mma_tf32(float* d, const uint32_t* a, uint32_t b0, uint32_t b1) {
    asm volatile(
        "mma.sync.aligned.m16n8k8.row.col.f32.tf32.tf32.f32 "
        "{%0,%1,%2,%3}, {%4,%5,%6,%7}, {%8,%9}, {%0,%1,%2,%3};"
        : "+f"(d[0]), "+f"(d[1]), "+f"(d[2]), "+f"(d[3])
        : "r"(a[0]), "r"(a[1]), "r"(a[2]), "r"(a[3]), "r"(b0), "r"(b1));
}

__device__ __forceinline__ void cp_async16(void* dst, const void* src) {
    uint32_t d;
    asm("{ .reg .u64 t; cvta.to.shared.u64 t, %1; cvt.u32.u64 %0, t; }" : "=r"(d) : "l"(dst));
    asm volatile("cp.async.cg.shared.global [%0], [%1], 16;" :: "r"(d), "l"(src) : "memory");
}
__device__ __forceinline__ void cp_commit() {
    asm volatile("cp.async.commit_group;" ::: "memory");
}
template <int N> __device__ __forceinline__ void cp_wait() {
    asm volatile("cp.async.wait_group %0;" :: "n"(N) : "memory");
}

// ---------------------------------------------------------------------------
__global__ void round_copy(const float* __restrict__ in, float* __restrict__ out, int n4) {
    int i = blockIdx.x * 256 + threadIdx.x;
    if (i < n4) {
        float4 v = ((const float4*)in)[i];
        v.x = f2tff(v.x); v.y = f2tff(v.y); v.z = f2tff(v.z); v.w = f2tff(v.w);
        ((float4*)out)[i] = v;
    }
}

__global__ void transpose_cvt(const float* __restrict__ in, float* __restrict__ out,
                              int R, int C) {
    __shared__ float t[32][33];
    int c0 = blockIdx.x * 32, r0 = blockIdx.y * 32;
    for (int i = threadIdx.y; i < 32; i += 8)
        t[i][threadIdx.x] = in[(size_t)(r0 + i) * C + c0 + threadIdx.x];
    __syncthreads();
    for (int i = threadIdx.y; i < 32; i += 8)
        out[(size_t)(c0 + i) * R + r0 + threadIdx.x] = f2tff(t[threadIdx.x][i]);
}

// ---------------------------------------------------------------------------
// tf32 mma.sync GEMM + bias: C[M,N] = A[M,K] @ Bt[N,K]^T + bias[N]
// CTA 128x128, BK=32, 128 thr = 4 warps (2m x 2n), warp tile 64x64.
// 2-stage cp.async pipeline. Optional tf32 rounding of output.
// ---------------------------------------------------------------------------
#define GST    36
#define GTILE  (128 * GST)             // 4608 floats per operand tile
#define GSTAGE (2 * GTILE)             // 9216 floats per stage
#define GSMEM_BYTES (2 * GSTAGE * 4)   // 73728 B

__global__ __launch_bounds__(128) void gemm_tf32(
    const float* __restrict__ A, const float* __restrict__ Bt,
    const float* __restrict__ bias, float* __restrict__ C,
    int M, int N, int K, int roundOut)
{
    extern __shared__ float sm[];
    const int tid  = threadIdx.x;
    const int wid  = tid >> 5, lane = tid & 31;
    const int g    = lane >> 2, c = lane & 3;
    const int wm   = wid & 1,  wn = wid >> 1;
    const int m0   = blockIdx.y * 128, n0 = blockIdx.x * 128;
    const int NCH  = K >> 5;

    float acc[4][8][4];
    #pragma unroll
    for (int i = 0; i < 4; i++)
        #pragma unroll
        for (int j = 0; j < 8; j++)
            #pragma unroll
            for (int k = 0; k < 4; k++) acc[i][j][k] = 0.f;

    // stage loader: per operand 128 rows x 8 f4 = 1024 f4; 128 thr -> 8 each
    auto load_stage = [&](int ch, int s) {
        float* sA = sm + s * GSTAGE;
        float* sB = sA + GTILE;
        const float* gA = A  + (size_t)m0 * K + ch * 32;
        const float* gB = Bt + (size_t)n0 * K + ch * 32;
        #pragma unroll
        for (int it = 0; it < 8; it++) {
            int idx = it * 128 + tid;
            int row = idx >> 3, c4 = (idx & 7) << 2;
            cp_async16(sA + row * GST + c4, gA + (size_t)row * K + c4);
            cp_async16(sB + row * GST + c4, gB + (size_t)row * K + c4);
        }
    };

    load_stage(0, 0);
    cp_commit();

    for (int ch = 0; ch < NCH; ch++) {
        if (ch + 1 < NCH) {
            load_stage(ch + 1, (ch + 1) & 1);
            cp_commit();
            cp_wait<1>();
        } else {
            cp_wait<0>();
        }
        __syncthreads();

        const float* sA = sm + (ch & 1) * GSTAGE;
        const float* sB = sA + GTILE;
        #pragma unroll
        for (int kf = 0; kf < 4; kf++) {
            uint32_t a[4][4];
            #pragma unroll
            for (int mf = 0; mf < 4; mf++) {
                const float* p = sA + (wm * 64 + mf * 16 + g) * GST + kf * 8 + c;
                a[mf][0] = __float_as_uint(p[0]);
                a[mf][1] = __float_as_uint(p[8 * GST]);
                a[mf][2] = __float_as_uint(p[4]);
                a[mf][3] = __float_as_uint(p[8 * GST + 4]);
            }
            #pragma unroll
            for (int nf = 0; nf < 8; nf++) {
                const float* p = sB + (wn * 64 + nf * 8 + g) * GST + kf * 8 + c;
                uint32_t b0 = __float_as_uint(p[0]);
                uint32_t b1 = __float_as_uint(p[4]);
                #pragma unroll
                for (int mf = 0; mf < 4; mf++)
                    mma_tf32(acc[mf][nf], a[mf], b0, b1);
            }
        }
        __syncthreads();
    }

    // epilogue (+bias, optional tf32 rounding for MMA-consumed outputs)
    #pragma unroll
    for (int mf = 0; mf < 4; mf++) {
        int r0 = m0 + wm * 64 + mf * 16 + g;
        #pragma unroll
        for (int nf = 0; nf < 8; nf++) {
            int cb = n0 + wn * 64 + nf * 8 + 2 * c;
            float2 bi = *(const float2*)(bias + cb);
            float2 v0 = { acc[mf][nf][0] + bi.x, acc[mf][nf][1] + bi.y };
            float2 v1 = { acc[mf][nf][2] + bi.x, acc[mf][nf][3] + bi.y };
            if (roundOut) {
                v0.x = f2tff(v0.x); v0.y = f2tff(v0.y);
                v1.x = f2tff(v1.x); v1.y = f2tff(v1.y);
            }
            *(float2*)(C + (size_t)r0 * N + cb)       = v0;
            *(float2*)(C + (size_t)(r0 + 8) * N + cb) = v1;
        }
    }
}

// ---------------------------------------------------------------------------
// Flash MQA, mma.sync tf32. BM=128 q-rows, BN=64 keys, d=128.
// 128 thr = 4 warps, warp tile 32q x 64k (regs: acc 128 + scores 64).
// K/V double-buffered via cp.async (pre-rounded to tf32 by K/V-proj epilogue).
// smem: s_q[128][132]; K slots 2x8704 (tile [64][132], P alias 4x[32][68]);
// V slots 2x[64][136]. Total 51712 floats = 206848 B -> 1 CTA/SM.
// ---------------------------------------------------------------------------
#define FQS 132
#define FKS 132
#define FVS 136
#define FPS 68
#define OFF_K0 16896
#define OFF_V0 34304
#define KSLOT  8704
#define FLASH_BYTES ((OFF_V0 + 2 * KSLOT) * 4)   // 206848

__global__ __launch_bounds__(128) void mqa_flash(
    const float* __restrict__ gQ, const float* __restrict__ gK,
    const float* __restrict__ gV, float* __restrict__ gO)
{
    extern __shared__ float sm[];
    float* s_q = sm;

    const int tid = threadIdx.x;
    const int wid = tid >> 5, lane = tid & 31;
    const int g = lane >> 2, c = lane & 3;

    const int b = blockIdx.z, h = blockIdx.y, q0 = blockIdx.x * 128;
    const float scale = 0.08838834764831845f;   // 1/sqrt(128)

    // stage Q (scaled + tf32 rounded): 128 rows x 32 f4 / 128 thr = 32 each
    const float* qg = gQ + (size_t)(b * SEQ + q0) * D_MODEL + h * HDIM;
    #pragma unroll
    for (int it = 0; it < 32; it++) {
        int i = it * 128 + tid;
        int row = i >> 5, dq = (i & 31) << 2;
        float4 v = *(const float4*)(qg + (size_t)row * D_MODEL + dq);
        s_q[row * FQS + dq + 0] = f2tff(v.x * scale);
        s_q[row * FQS + dq + 1] = f2tff(v.y * scale);
        s_q[row * FQS + dq + 2] = f2tff(v.z * scale);
        s_q[row * FQS + dq + 3] = f2tff(v.w * scale);
    }

    // K/V tile stage via cp.async (raw bytes; data pre-rounded)
    auto load_kv = [&](int kt, int buf) {
        float* s_k = sm + OFF_K0 + buf * KSLOT;
        float* s_v = sm + OFF_V0 + buf * KSLOT;
        const float* kg = gK + (size_t)(b * SEQ + kt) * HDIM;
        const float* vg = gV + (size_t)(b * SEQ + kt) * HDIM;
        #pragma unroll
        for (int it = 0; it < 16; it++) {
            int i = it * 128 + tid;
            int row = i >> 5, dq = (i & 31) << 2;
            cp_async16(s_k + row * FKS + dq, kg + row * HDIM + dq);
            cp_async16(s_v + row * FVS + dq, vg + row * HDIM + dq);
        }
    };

    float m_i[4], l_i[4], acc[2][16][4];
    #pragma unroll
    for (int r = 0; r < 4; r++) { m_i[r] = -1e30f; l_i[r] = 0.f; }
    #pragma unroll
    for (int mf = 0; mf < 2; mf++)
        #pragma unroll
        for (int nf = 0; nf < 16; nf++)
            #pragma unroll
            for (int j = 0; j < 4; j++) acc[mf][nf][j] = 0.f;

    load_kv(0, 0);
    cp_commit();

    const int NT = SEQ / 64;
    for (int t = 0; t < NT; t++) {
        int buf = t & 1;
        if (t + 1 < NT) {
            load_kv((t + 1) * 64, buf ^ 1);
            cp_commit();
            cp_wait<1>();
        } else {
            cp_wait<0>();
        }
        __syncthreads();   // tile t data visible; prev buf fully consumed

        const float* s_k = sm + OFF_K0 + buf * KSLOT;
        const float* s_v = sm + OFF_V0 + buf * KSLOT;
        float* s_p = sm + OFF_K0 + buf * KSLOT + wid * 32 * FPS;  // alias

        // --- scores: S[32 x 64] per warp ---
        float sf[2][8][4];
        #pragma unroll
        for (int mf = 0; mf < 2; mf++)
            #pragma unroll
            for (int nf = 0; nf < 8; nf++)
                #pragma unroll
                for (int j = 0; j < 4; j++) sf[mf][nf][j] = 0.f;

        #pragma unroll
        for (int kf = 0; kf < 16; kf++) {
            uint32_t a[2][4];
            #pragma unroll
            for (int mf = 0; mf < 2; mf++) {
                const float* p = s_q + (wid * 32 + mf * 16 + g) * FQS + kf * 8 + c;
                a[mf][0] = __float_as_uint(p[0]);
                a[mf][1] = __float_as_uint(p[8 * FQS]);
                a[mf][2] = __float_as_uint(p[4]);
                a[mf][3] = __float_as_uint(p[8 * FQS + 4]);
            }
            #pragma unroll
            for (int nf = 0; nf < 8; nf++) {
                const float* q = s_k + (nf * 8 + g) * FKS + kf * 8 + c;
                uint32_t b0 = __float_as_uint(q[0]);
                uint32_t b1 = __float_as_uint(q[4]);
                #pragma unroll
                for (int mf = 0; mf < 2; mf++)
                    mma_tf32(sf[mf][nf], a[mf], b0, b1);
            }
        }
        __syncthreads();   // all warps done reading s_k -> safe to alias P

        // --- online softmax; row r = mf*2 + half, rows (wid*32+mf*16+g+half*8)
        float tmax[4] = {-1e30f, -1e30f, -1e30f, -1e30f};
        #pragma unroll
        for (int mf = 0; mf < 2; mf++)
            #pragma unroll
            for (int nf = 0; nf < 8; nf++) {
                tmax[mf * 2 + 0] = fmaxf(tmax[mf * 2 + 0], fmaxf(sf[mf][nf][0], sf[mf][nf][1]));
                tmax[mf * 2 + 1] = fmaxf(tmax[mf * 2 + 1], fmaxf(sf[mf][nf][2], sf[mf][nf][3]));
            }
        #pragma unroll
        for (int off = 1; off <= 2; off <<= 1)
            #pragma unroll
            for (int r = 0; r < 4; r++)
                tmax[r] = fmaxf(tmax[r], __shfl_xor_sync(0xffffffffu, tmax[r], off));

        float corr[4], rs[4] = {0.f, 0.f, 0.f, 0.f};
        #pragma unroll
        for (int r = 0; r < 4; r++) {
            float mn = fmaxf(m_i[r], tmax[r]);
            corr[r] = __expf(m_i[r] - mn);
            m_i[r] = mn;
        }
        #pragma unroll
        for (int mf = 0; mf < 2; mf++)
            #pragma unroll
            for (int nf = 0; nf < 8; nf++) {
                sf[mf][nf][0] = __expf(sf[mf][nf][0] - m_i[mf * 2 + 0]);
                sf[mf][nf][1] = __expf(sf[mf][nf][1] - m_i[mf * 2 + 0]);
                sf[mf][nf][2] = __expf(sf[mf][nf][2] - m_i[mf * 2 + 1]);
                sf[mf][nf][3] = __expf(sf[mf][nf][3] - m_i[mf * 2 + 1]);
                rs[mf * 2 + 0] += sf[mf][nf][0] + sf[mf][nf][1];
                rs[mf * 2 + 1] += sf[mf][nf][2] + sf[mf][nf][3];
            }
        #pragma unroll
        for (int off = 1; off <= 2; off <<= 1)
            #pragma unroll
            for (int r = 0; r < 4; r++)
                rs[r] += __shfl_xor_sync(0xffffffffu, rs[r], off);
        #pragma unroll
        for (int r = 0; r < 4; r++) l_i[r] = l_i[r] * corr[r] + rs[r];

        #pragma unroll
        for (int mf = 0; mf < 2; mf++)
            #pragma unroll
            for (int nf = 0; nf < 16; nf++) {
                acc[mf][nf][0] *= corr[mf * 2 + 0];  acc[mf][nf][1] *= corr[mf * 2 + 0];
                acc[mf][nf][2] *= corr[mf * 2 + 1];  acc[mf][nf][3] *= corr[mf * 2 + 1];
            }

        // store P (tf32-rounded) into per-warp alias tile [32][FPS]
        #pragma unroll
        for (int mf = 0; mf < 2; mf++)
            #pragma unroll
            for (int nf = 0; nf < 8; nf++) {
                uint2 w0 = { f2tf(sf[mf][nf][0]), f2tf(sf[mf][nf][1]) };
                uint2 w1 = { f2tf(sf[mf][nf][2]), f2tf(sf[mf][nf][3]) };
                *(uint2*)(s_p + (mf * 16 + g) * FPS + nf * 8 + 2 * c)     = w0;
                *(uint2*)(s_p + (mf * 16 + g + 8) * FPS + nf * 8 + 2 * c) = w1;
            }
        __syncwarp();

        // --- PV: acc[32 x 128] += P[32 x 64] @ V[64 x 128] ---
        #pragma unroll
        for (int kf = 0; kf < 8; kf++) {
            uint32_t a[2][4];
            #pragma unroll
            for (int mf = 0; mf < 2; mf++) {
                const float* p = s_p + (mf * 16 + g) * FPS + kf * 8 + c;
                a[mf][0] = __float_as_uint(p[0]);
                a[mf][1] = __float_as_uint(p[8 * FPS]);
                a[mf][2] = __float_as_uint(p[4]);
                a[mf][3] = __float_as_uint(p[8 * FPS + 4]);
            }
            #pragma unroll
            for (int nf = 0; nf < 16; nf++) {
                const float* q = s_v + (kf * 8 + c) * FVS + nf * 8 + g;
                uint32_t b0 = __float_as_uint(q[0]);
                uint32_t b1 = __float_as_uint(q[4 * FVS]);
                #pragma unroll
                for (int mf = 0; mf < 2; mf++)
                    mma_tf32(acc[mf][nf], a[mf], b0, b1);
            }
        }
        __syncthreads();   // P & V consumed before next prefetch overwrites
    }

    // epilogue: normalize + tf32-round (feeds O-proj as A operand)
    #pragma unroll
    for (int mf = 0; mf < 2; mf++) {
        float inv0 = 1.f / l_i[mf * 2 + 0];
        float inv1 = 1.f / l_i[mf * 2 + 1];
        float* o0 = gO + (size_t)(b * SEQ + q0 + wid * 32 + mf * 16 + g) * D_MODEL + h * HDIM;
        float* o1 = o0 + 8 * D_MODEL;
        #pragma unroll
        for (int nf = 0; nf < 16; nf++) {
            int cb = nf * 8 + 2 * c;
            float2 v0 = { f2tff(acc[mf][nf][0] * inv0), f2tff(acc[mf][nf][1] * inv0) };
            float2 v1 = { f2tff(acc[mf][nf][2] * inv1), f2tff(acc[mf][nf][3] * inv1) };
            *(float2*)(o0 + cb) = v0;
            *(float2*)(o1 + cb) = v1;
        }
    }
}

// ---------------------------------------------------------------------------
extern "C" void kernel_launch(void* const* d_in, const int* in_sizes, int n_in,
                              void* d_out, int out_size)
{
    const float* query = (const float*)d_in[0];
    const float* key   = (const float*)d_in[1];
    const float* value = (const float*)d_in[2];
    const float* Wq    = (const float*)d_in[3];
    const float* bq    = (const float*)d_in[4];
    const float* Wk    = (const float*)d_in[5];
    const float* bk    = (const float*)d_in[6];
    const float* Wv    = (const float*)d_in[7];
    const float* bv    = (const float*)d_in[8];
    const float* Wo    = (const float*)d_in[9];
    const float* bo    = (const float*)d_in[10];
    float* out = (float*)d_out;

    float *pQ, *pK, *pV, *pA, *pQr, *pKr, *pVr, *pWqt, *pWot, *pWkt, *pWvt;
    cudaGetSymbolAddress((void**)&pQ,  g_Q);
    cudaGetSymbolAddress((void**)&pK,  g_K);
    cudaGetSymbolAddress((void**)&pV,  g_V);
    cudaGetSymbolAddress((void**)&pA,  g_A);
    cudaGetSymbolAddress((void**)&pQr, g_Qr);
    cudaGetSymbolAddress((void**)&pKr, g_Kr);
    cudaGetSymbolAddress((void**)&pVr, g_Vr);
    cudaGetSymbolAddress((void**)&pWqt, g_Wqt);
    cudaGetSymbolAddress((void**)&pWot, g_Wot);
    cudaGetSymbolAddress((void**)&pWkt, g_Wkt);
    cudaGetSymbolAddress((void**)&pWvt, g_Wvt);

    cudaFuncSetAttribute(gemm_tf32, cudaFuncAttributeMaxDynamicSharedMemorySize, GSMEM_BYTES);
    cudaFuncSetAttribute(mqa_flash, cudaFuncAttributeMaxDynamicSharedMemorySize, FLASH_BYTES);

    const int n4 = MTOT * D_MODEL / 4;
    round_copy<<<n4 / 256, 256>>>(query, pQr, n4);
    round_copy<<<n4 / 256, 256>>>(key,   pKr, n4);
    round_copy<<<n4 / 256, 256>>>(value, pVr, n4);

    dim3 tb(32, 8);
    transpose_cvt<<<dim3(D_MODEL / 32, D_MODEL / 32), tb>>>(Wq, pWqt, D_MODEL, D_MODEL);
    transpose_cvt<<<dim3(HDIM / 32,    D_MODEL / 32), tb>>>(Wk, pWkt, D_MODEL, HDIM);
    transpose_cvt<<<dim3(HDIM / 32,    D_MODEL / 32), tb>>>(Wv, pWvt, D_MODEL, HDIM);
    transpose_cvt<<<dim3(D_MODEL / 32, D_MODEL / 32), tb>>>(Wo, pWot, D_MODEL, D_MODEL);

    // Projections. K/V outputs tf32-rounded (consumed raw by flash cp.async).
    gemm_tf32<<<dim3(D_MODEL / 128, MTOT / 128), 128, GSMEM_BYTES>>>(pQr, pWqt, bq, pQ, MTOT, D_MODEL, D_MODEL, 0);
    gemm_tf32<<<dim3(1,             MTOT / 128), 128, GSMEM_BYTES>>>(pKr, pWkt, bk, pK, MTOT, HDIM,    D_MODEL, 1);
    gemm_tf32<<<dim3(1,             MTOT / 128), 128, GSMEM_BYTES>>>(pVr, pWvt, bv, pV, MTOT, HDIM,    D_MODEL, 1);

    mqa_flash<<<dim3(SEQ / 128, NHEAD, BATCH), 128, FLASH_BYTES>>>(pQ, pK, pV, pA);

    gemm_tf32<<<dim3(D_MODEL / 128, MTOT / 128), 128, GSMEM_BYTES>>>(pA, pWot, bo, out, MTOT, D_MODEL, D_MODEL, 0);
}